// round 15
// baseline (speedup 1.0000x reference)
#include <cuda_runtime.h>
#include <cuda_bf16.h>
#include <cstdint>

constexpr int B_ = 2, N_ = 2048, E_ = 1024, H_ = 16;
constexpr int BH = 32;

// scratch — all head tensors are [row][32 words] (word w = dims 2w,2w+1)
__device__ uint32_t g_q16[BH * N_ * 32];       // Q heads, bf16x2, pre-scaled by log2e/32
__device__ uint32_t g_k16[BH * N_ * 32];       // K heads, bf16x2
__device__ uint32_t g_v16[BH * N_ * 32];       // V heads, fp16x2
__device__ uint32_t g_at16[B_ * N_ * E_ / 2];  // attention out, fp16x2
__device__ uint32_t g_wo16[E_ * E_ / 2];       // Wo, fp16x2

__device__ __forceinline__ uint32_t packbf(float lo, float hi) {
    uint32_t d; asm("cvt.rn.bf16x2.f32 %0, %1, %2;" : "=r"(d) : "f"(hi), "f"(lo));
    return d;
}
__device__ __forceinline__ uint32_t packh(float lo, float hi) {
    uint32_t d; asm("cvt.rn.f16x2.f32 %0, %1, %2;" : "=r"(d) : "f"(hi), "f"(lo));
    return d;
}
__device__ __forceinline__ float ex2(float x) {
    float r; asm("ex2.approx.ftz.f32 %0, %1;" : "=f"(r) : "f"(x));
    return r;
}
__device__ __forceinline__ uint32_t prmt(uint32_t a, uint32_t b, uint32_t sel) {
    uint32_t d; asm("prmt.b32 %0, %1, %2, %3;" : "=r"(d) : "r"(a), "r"(b), "r"(sel));
    return d;
}
__device__ __forceinline__ void mma_bf16(float c[4],
    uint32_t a0, uint32_t a1, uint32_t a2, uint32_t a3, uint32_t b0, uint32_t b1)
{
    asm volatile(
        "mma.sync.aligned.m16n8k16.row.col.f32.bf16.bf16.f32 "
        "{%0,%1,%2,%3}, {%4,%5,%6,%7}, {%8,%9}, {%0,%1,%2,%3};"
        : "+f"(c[0]), "+f"(c[1]), "+f"(c[2]), "+f"(c[3])
        : "r"(a0), "r"(a1), "r"(a2), "r"(a3), "r"(b0), "r"(b1));
}
__device__ __forceinline__ void mma_f16(float c[4],
    uint32_t a0, uint32_t a1, uint32_t a2, uint32_t a3, uint32_t b0, uint32_t b1)
{
    asm volatile(
        "mma.sync.aligned.m16n8k16.row.col.f32.f16.f16.f32 "
        "{%0,%1,%2,%3}, {%4,%5,%6,%7}, {%8,%9}, {%0,%1,%2,%3};"
        : "+f"(c[0]), "+f"(c[1]), "+f"(c[2]), "+f"(c[3])
        : "r"(a0), "r"(a1), "r"(a2), "r"(a3), "r"(b0), "r"(b1));
}
__device__ __forceinline__ void cpa16(uint32_t dst_smem, const void* src) {
    asm volatile("cp.async.cg.shared.global [%0], [%1], 16;" :: "r"(dst_smem), "l"(src));
}
__device__ __forceinline__ uint32_t smem_u32(const void* p) {
    uint32_t r;
    asm("{ .reg .u64 tmp; cvta.to.shared.u64 tmp, %1; cvt.u32.u64 %0, tmp; }"
        : "=r"(r) : "l"(p));
    return r;
}

// ---------------------------------------------------------------------------
// Kernel 0: pack Wo to fp16x2 words.
// ---------------------------------------------------------------------------
__global__ __launch_bounds__(256) void wo_prep(const float* __restrict__ Wo)
{
    int i = (blockIdx.x * 256 + threadIdx.x) * 4;
    float4 v = *(const float4*)&Wo[i];
    *(uint2*)&g_wo16[i >> 1] = make_uint2(packh(v.x, v.y), packh(v.z, v.w));
}

// ---------------------------------------------------------------------------
// Kernel 1: per-head projections via fp16 m16n8k16 mma (halved mma count,
// halved SMEM vs tf32). Q gets log2e/32 folded before its bf16 rounding.
// Q/K out bf16x2; V out fp16x2. grid (32, BH, 3), block 128.
// ---------------------------------------------------------------------------
__global__ __launch_bounds__(128) void proj_kernel(
    const float* __restrict__ Q, const float* __restrict__ K, const float* __restrict__ V,
    const float* __restrict__ Wq, const float* __restrict__ Wk, const float* __restrict__ Wv)
{
    __shared__ __align__(16) uint32_t Xs[64 * 36];   // fp16x2 words, stride 36
    __shared__ __align__(16) uint32_t Ws[64 * 36];

    int which = blockIdx.z;
    const float* X = (which == 0) ? Q : (which == 1) ? K : V;
    const float* W = (which == 0) ? Wq : (which == 1) ? Wk : Wv;
    int bh = blockIdx.y, b = bh >> 4, h = bh & 15;
    int n0 = blockIdx.x * 64;
    int t = threadIdx.x, w = t >> 5, lane = t & 31, g = lane >> 2, tig = lane & 3;

    const float* Xb = X + ((size_t)b * N_ + n0) * E_ + h * 64;
    for (int idx = t; idx < 1024; idx += 128) {
        int r = idx >> 4, j = idx & 15;                    // j = float4 index
        float4 x = *(const float4*)&Xb[(size_t)r * E_ + j * 4];
        *(uint2*)&Xs[r * 36 + 2 * j] = make_uint2(packh(x.x, x.y), packh(x.z, x.w));
    }
    for (int idx = t; idx < 2048; idx += 128) {
        int r = idx >> 5, wd = idx & 31;
        float2 v = *(const float2*)&W[h * 4096 + r * 64 + 2 * wd];
        Ws[r * 36 + wd] = packh(v.x, v.y);
    }
    __syncthreads();

    int r_lo = w * 16 + g, r_hi = r_lo + 8;
    float o[8][4] = {};
    #pragma unroll
    for (int kk = 0; kk < 4; kk++) {
        uint32_t a0 = Xs[r_lo * 36 + kk * 8 + tig];
        uint32_t a1 = Xs[r_hi * 36 + kk * 8 + tig];
        uint32_t a2 = Xs[r_lo * 36 + kk * 8 + tig + 4];
        uint32_t a3 = Xs[r_hi * 36 + kk * 8 + tig + 4];
        #pragma unroll
        for (int nt = 0; nt < 8; nt++) {
            uint32_t b0 = Ws[(nt * 8 + g) * 36 + kk * 8 + tig];
            uint32_t b1 = Ws[(nt * 8 + g) * 36 + kk * 8 + tig + 4];
            mma_f16(o[nt], a0, a1, a2, a3, b0, b1);
        }
    }
    size_t rb = (size_t)bh * N_ + n0;
    if (which == 2) {
        #pragma unroll
        for (int nt = 0; nt < 8; nt++) {
            g_v16[(rb + r_lo) * 32 + nt * 4 + tig] = packh(o[nt][0], o[nt][1]);
            g_v16[(rb + r_hi) * 32 + nt * 4 + tig] = packh(o[nt][2], o[nt][3]);
        }
    } else {
        uint32_t* dst = (which == 0) ? g_q16 : g_k16;
        const float C = (which == 0) ? 0.045084220027780106f : 1.0f;  // log2e/32 into Q
        #pragma unroll
        for (int nt = 0; nt < 8; nt++) {
            dst[(rb + r_lo) * 32 + nt * 4 + tig] = packbf(o[nt][0] * C, o[nt][1] * C);
            dst[(rb + r_hi) * 32 + nt * 4 + tig] = packbf(o[nt][2] * C, o[nt][3] * C);
        }
    }
}

// ---------------------------------------------------------------------------
// Kernel 2: flash attention, no-max softmax, raw MUFU.EX2.
// CTA = 256 q-rows x 64 keys; 8 warps x 32 rows.
// S: bf16 m16n8k16 (pre-scaled Q, masked rows zeroed via AND).
// PV: fp16 m16n8k16; P packed straight from registers (C-frag == A-frag).
// V: fp16 from proj; re-paired d-pairs -> key-pairs with 2 PRMT per word pair.
// grid (8, BH), block 256.
// ---------------------------------------------------------------------------
constexpr int KS_W = 64 * 36;
constexpr int VT_W = 32 * 72;

__global__ __launch_bounds__(256) void attn_kernel(const int* __restrict__ mask)
{
    __shared__ __align__(16) uint32_t Ks16[2][KS_W];
    __shared__ __align__(16) uint32_t Vt[2][VT_W];
    uint32_t kb_base = smem_u32(&Ks16[0][0]);

    int bh = blockIdx.y, b = bh >> 4, h = bh & 15;
    int q0 = blockIdx.x * 256;
    int t = threadIdx.x, wid = t >> 5, lane = t & 31, g = lane >> 2, tig = lane & 3;
    const uint32_t FULL = 0xffffffffu;

    int r0 = wid * 32 + g;
    int rows[4] = {r0, r0 + 8, r0 + 16, r0 + 24};
    uint32_t msk[4];
    #pragma unroll
    for (int i = 0; i < 4; i++)
        msk[i] = mask[b * N_ + q0 + rows[i]] ? 0xffffffffu : 0u;

    const uint32_t* Qg = g_q16 + ((size_t)bh * N_ + q0) * 32;
    uint32_t qa[2][4][4];
    #pragma unroll
    for (int m = 0; m < 2; m++)
        #pragma unroll
        for (int kk = 0; kk < 4; kk++) {
            qa[m][kk][0] = Qg[(size_t)rows[2*m]   * 32 + kk * 8 + tig]     & msk[2*m];
            qa[m][kk][1] = Qg[(size_t)rows[2*m+1] * 32 + kk * 8 + tig]     & msk[2*m+1];
            qa[m][kk][2] = Qg[(size_t)rows[2*m]   * 32 + kk * 8 + tig + 4] & msk[2*m];
            qa[m][kk][3] = Qg[(size_t)rows[2*m+1] * 32 + kk * 8 + tig + 4] & msk[2*m+1];
        }

    const uint32_t* Kg = g_k16 + (size_t)bh * N_ * 32;
    const uint32_t* Vg = g_v16 + (size_t)bh * N_ * 32;

    auto prefK = [&](int kt, int buf) {
        const uint32_t* kg = Kg + kt * 64 * 32;
        uint32_t kb = kb_base + buf * (KS_W * 4);
        #pragma unroll
        for (int i = t; i < 512; i += 256) {
            int row = i >> 3, c = (i & 7) * 4;
            cpa16(kb + (row * 36 + c) * 4, &kg[row * 32 + c]);
        }
        asm volatile("cp.async.commit_group;");
    };

    // V prefetch: lane = d-pair word (0..31), kp = wid + 8*i (key pair)
    uint32_t vA[4], vB[4];
    auto ldV = [&](int kt) {
        const uint32_t* vg = Vg + kt * 64 * 32;
        #pragma unroll
        for (int i = 0; i < 4; i++) {
            int kp = wid + 8 * i;
            vA[i] = vg[(2 * kp) * 32 + lane];        // key 2kp,   d 2lane..2lane+1
            vB[i] = vg[(2 * kp + 1) * 32 + lane];    // key 2kp+1
        }
    };
    auto stV = [&](int buf) {
        #pragma unroll
        for (int i = 0; i < 4; i++) {
            int kp = wid + 8 * i;
            uint32_t w0 = prmt(vA[i], vB[i], 0x5410);   // (v[2kp][d], v[2kp+1][d]), d=2lane
            uint32_t w1 = prmt(vA[i], vB[i], 0x7632);   // d=2lane+1
            *(uint2*)&Vt[buf][kp * 72 + 2 * lane] = make_uint2(w0, w1);
        }
    };

    float o[2][8][4] = {};
    float lr[4] = {};

    prefK(0, 0);
    ldV(0);
    for (int kt = 0; kt < 32; kt++) {
        int buf = kt & 1;
        stV(buf);
        asm volatile("cp.async.wait_group 0;");
        __syncthreads();
        if (kt + 1 < 32) { prefK(kt + 1, buf ^ 1); ldV(kt + 1); }
        const uint32_t* Kb = Ks16[buf];
        const uint32_t* Vb = Vt[buf];

        // ---- S = (Q*log2e/32) K^T (bf16 m16n8k16) ----
        float s[2][8][4] = {};
        #pragma unroll
        for (int kk = 0; kk < 4; kk++)
            #pragma unroll
            for (int nt = 0; nt < 8; nt++) {
                uint32_t b0 = Kb[(nt * 8 + g) * 36 + kk * 8 + tig];
                uint32_t b1 = Kb[(nt * 8 + g) * 36 + kk * 8 + tig + 4];
                mma_bf16(s[0][nt], qa[0][kk][0], qa[0][kk][1], qa[0][kk][2], qa[0][kk][3], b0, b1);
                mma_bf16(s[1][nt], qa[1][kk][0], qa[1][kk][1], qa[1][kk][2], qa[1][kk][3], b0, b1);
            }

        // ---- p = 2^s via raw MUFU.EX2 (no max: |s| << 1), partial l ----
        #pragma unroll
        for (int m = 0; m < 2; m++)
            #pragma unroll
            for (int nt = 0; nt < 8; nt++) {
                s[m][nt][0] = ex2(s[m][nt][0]);
                s[m][nt][1] = ex2(s[m][nt][1]);
                s[m][nt][2] = ex2(s[m][nt][2]);
                s[m][nt][3] = ex2(s[m][nt][3]);
                lr[2*m]   += s[m][nt][0] + s[m][nt][1];
                lr[2*m+1] += s[m][nt][2] + s[m][nt][3];
            }

        // ---- O += P @ V (fp16 m16n8k16, P packed straight from registers) ----
        #pragma unroll
        for (int kk = 0; kk < 4; kk++) {
            uint32_t pa[2][4];
            #pragma unroll
            for (int m = 0; m < 2; m++) {
                pa[m][0] = packh(s[m][2*kk][0],   s[m][2*kk][1]);
                pa[m][1] = packh(s[m][2*kk][2],   s[m][2*kk][3]);
                pa[m][2] = packh(s[m][2*kk+1][0], s[m][2*kk+1][1]);
                pa[m][3] = packh(s[m][2*kk+1][2], s[m][2*kk+1][3]);
            }
            #pragma unroll
            for (int nt = 0; nt < 8; nt++) {
                uint32_t b0 = Vb[(kk * 8 + tig) * 72 + nt * 8 + g];
                uint32_t b1 = Vb[(kk * 8 + tig + 4) * 72 + nt * 8 + g];
                mma_f16(o[0][nt], pa[0][0], pa[0][1], pa[0][2], pa[0][3], b0, b1);
                mma_f16(o[1][nt], pa[1][0], pa[1][1], pa[1][2], pa[1][3], b0, b1);
            }
        }
    }

    // deferred l-reduction
    float il[4];
    #pragma unroll
    for (int i = 0; i < 4; i++) {
        lr[i] += __shfl_xor_sync(FULL, lr[i], 1);
        lr[i] += __shfl_xor_sync(FULL, lr[i], 2);
        il[i] = 1.f / lr[i];
    }
    uint32_t* ob = g_at16 + ((size_t)b * N_ + q0) * 512 + h * 32;
    #pragma unroll
    for (int m = 0; m < 2; m++)
        #pragma unroll
        for (int nt = 0; nt < 8; nt++) {
            ob[(size_t)rows[2*m]   * 512 + nt * 4 + tig] =
                packh(o[m][nt][0] * il[2*m],   o[m][nt][1] * il[2*m]);
            ob[(size_t)rows[2*m+1] * 512 + nt * 4 + tig] =
                packh(o[m][nt][2] * il[2*m+1], o[m][nt][3] * il[2*m+1]);
        }
}

// ---------------------------------------------------------------------------
// Kernel 3: out = attn @ Wo^T, fp16 m16n8k16 (unchanged, 37us).
// grid (32, 8), block 256.
// ---------------------------------------------------------------------------
constexpr int OPH = 128 * 36;

__global__ __launch_bounds__(256) void oproj_kernel(float* __restrict__ out)
{
    extern __shared__ __align__(16) char smraw[];
    uint32_t* As = (uint32_t*)smraw;
    uint32_t* Ws = (uint32_t*)(smraw + 2 * OPH * 4);
    uint32_t smem_base = smem_u32(smraw);

    int rB = blockIdx.x * 128, cB = blockIdx.y * 128;
    int t = threadIdx.x, w = t >> 5, lane = t & 31, g = lane >> 2, tig = lane & 3;
    int wr = w >> 1, wc = w & 1;
    int row0 = wr * 32, col0 = wc * 64;

    auto prefetch = [&](int e0w, int buf) {
        uint32_t abase = smem_base + (buf * OPH) * 4;
        uint32_t wbase = smem_base + (2 * OPH + buf * OPH) * 4;
        #pragma unroll
        for (int i = t; i < 1024; i += 256) {
            int r = i >> 3, c = (i & 7) * 4;
            cpa16(abase + (r * 36 + c) * 4, &g_at16[(size_t)(rB + r) * 512 + e0w + c]);
        }
        #pragma unroll
        for (int i = t; i < 1024; i += 256) {
            int r = i >> 3, c = (i & 7) * 4;
            cpa16(wbase + (r * 36 + c) * 4, &g_wo16[(size_t)(cB + r) * 512 + e0w + c]);
        }
        asm volatile("cp.async.commit_group;");
    };

    float o[2][8][4] = {};
    prefetch(0, 0);
    for (int es = 0; es < 16; es++) {
        int buf = es & 1;
        if (es + 1 < 16) {
            prefetch((es + 1) * 32, buf ^ 1);
            asm volatile("cp.async.wait_group 1;");
        } else {
            asm volatile("cp.async.wait_group 0;");
        }
        __syncthreads();
        const uint32_t* Ab = As + buf * OPH;
        const uint32_t* Wb = Ws + buf * OPH;

        #pragma unroll
        for (int kk = 0; kk < 4; kk++) {
            uint32_t a[2][4];
            #pragma unroll
            for (int m = 0; m < 2; m++) {
                int ra = row0 + 16 * m + g;
                a[m][0] = Ab[ra * 36 + kk * 8 + tig];
                a[m][1] = Ab[(ra + 8) * 36 + kk * 8 + tig];
                a[m][2] = Ab[ra * 36 + kk * 8 + tig + 4];
                a[m][3] = Ab[(ra + 8) * 36 + kk * 8 + tig + 4];
            }
            #pragma unroll
            for (int nt = 0; nt < 8; nt++) {
                uint32_t b0 = Wb[(col0 + nt * 8 + g) * 36 + kk * 8 + tig];
                uint32_t b1 = Wb[(col0 + nt * 8 + g) * 36 + kk * 8 + tig + 4];
                mma_f16(o[0][nt], a[0][0], a[0][1], a[0][2], a[0][3], b0, b1);
                mma_f16(o[1][nt], a[1][0], a[1][1], a[1][2], a[1][3], b0, b1);
            }
        }
        __syncthreads();
    }

    #pragma unroll
    for (int m = 0; m < 2; m++) {
        int ra = rB + row0 + 16 * m + g;
        #pragma unroll
        for (int nt = 0; nt < 8; nt++) {
            *(float2*)&out[(size_t)ra * E_ + cB + col0 + nt * 8 + 2 * tig] =
                make_float2(o[m][nt][0], o[m][nt][1]);
            *(float2*)&out[(size_t)(ra + 8) * E_ + cB + col0 + nt * 8 + 2 * tig] =
                make_float2(o[m][nt][2], o[m][nt][3]);
        }
    }
}

// ---------------------------------------------------------------------------
extern "C" void kernel_launch(void* const* d_in, const int* in_sizes, int n_in,
                              void* d_out, int out_size)
{
    const float* q    = (const float*)d_in[0];
    const float* k    = (const float*)d_in[1];
    const float* v    = (const float*)d_in[2];
    const int*   mask = (const int*)  d_in[3];
    const float* Wq   = (const float*)d_in[4];
    const float* Wk   = (const float*)d_in[5];
    const float* Wv   = (const float*)d_in[6];
    const float* Wo   = (const float*)d_in[7];
    float* out = (float*)d_out;

    int oproj_smem = 4 * OPH * 4;                            // 73728 B
    static int attr_set = 0;
    if (!attr_set) {
        cudaFuncSetAttribute(oproj_kernel, cudaFuncAttributeMaxDynamicSharedMemorySize, oproj_smem);
        attr_set = 1;
    }

    wo_prep<<<E_ * E_ / 1024, 256>>>(Wo);
    proj_kernel<<<dim3(N_ / 64, BH, 3), 128>>>(q, k, v, Wq, Wk, Wv);
    attn_kernel<<<dim3(N_ / 256, BH), 256>>>(mask);
    oproj_kernel<<<dim3(B_ * N_ / 128, E_ / 128), 256, oproj_smem>>>(out);
}

// round 17
// speedup vs baseline: 1.5025x; 1.5025x over previous
#include <cuda_runtime.h>
#include <cuda_bf16.h>
#include <cstdint>

constexpr int B_ = 2, N_ = 2048, E_ = 1024, H_ = 16;
constexpr int BH = 32;

// scratch — all head tensors are [row][32 words] (word w = dims 2w,2w+1)
__device__ uint32_t g_q16[BH * N_ * 32];       // Q heads, bf16x2, pre-scaled by log2e/32
__device__ uint32_t g_k16[BH * N_ * 32];       // K heads, bf16x2
__device__ uint32_t g_v16[BH * N_ * 32];       // V heads, fp16x2
__device__ uint32_t g_at16[B_ * N_ * E_ / 2];  // attention out, fp16x2
__device__ uint32_t g_wo16[E_ * E_ / 2];       // Wo, fp16x2

__device__ __forceinline__ uint32_t packbf(float lo, float hi) {
    uint32_t d; asm("cvt.rn.bf16x2.f32 %0, %1, %2;" : "=r"(d) : "f"(hi), "f"(lo));
    return d;
}
__device__ __forceinline__ uint32_t packh(float lo, float hi) {
    uint32_t d; asm("cvt.rn.f16x2.f32 %0, %1, %2;" : "=r"(d) : "f"(hi), "f"(lo));
    return d;
}
__device__ __forceinline__ float ex2(float x) {
    float r; asm("ex2.approx.ftz.f32 %0, %1;" : "=f"(r) : "f"(x));
    return r;
}
__device__ __forceinline__ uint32_t prmt(uint32_t a, uint32_t b, uint32_t sel) {
    uint32_t d; asm("prmt.b32 %0, %1, %2, %3;" : "=r"(d) : "r"(a), "r"(b), "r"(sel));
    return d;
}
__device__ __forceinline__ void mma_bf16(float c[4],
    uint32_t a0, uint32_t a1, uint32_t a2, uint32_t a3, uint32_t b0, uint32_t b1)
{
    asm volatile(
        "mma.sync.aligned.m16n8k16.row.col.f32.bf16.bf16.f32 "
        "{%0,%1,%2,%3}, {%4,%5,%6,%7}, {%8,%9}, {%0,%1,%2,%3};"
        : "+f"(c[0]), "+f"(c[1]), "+f"(c[2]), "+f"(c[3])
        : "r"(a0), "r"(a1), "r"(a2), "r"(a3), "r"(b0), "r"(b1));
}
__device__ __forceinline__ void mma_f16(float c[4],
    uint32_t a0, uint32_t a1, uint32_t a2, uint32_t a3, uint32_t b0, uint32_t b1)
{
    asm volatile(
        "mma.sync.aligned.m16n8k16.row.col.f32.f16.f16.f32 "
        "{%0,%1,%2,%3}, {%4,%5,%6,%7}, {%8,%9}, {%0,%1,%2,%3};"
        : "+f"(c[0]), "+f"(c[1]), "+f"(c[2]), "+f"(c[3])
        : "r"(a0), "r"(a1), "r"(a2), "r"(a3), "r"(b0), "r"(b1));
}
__device__ __forceinline__ void cpa16(uint32_t dst_smem, const void* src) {
    asm volatile("cp.async.cg.shared.global [%0], [%1], 16;" :: "r"(dst_smem), "l"(src));
}
__device__ __forceinline__ uint32_t smem_u32(const void* p) {
    uint32_t r;
    asm("{ .reg .u64 tmp; cvta.to.shared.u64 tmp, %1; cvt.u32.u64 %0, tmp; }"
        : "=r"(r) : "l"(p));
    return r;
}

// ---------------------------------------------------------------------------
// Kernel 0: pack Wo to fp16x2 words.
// ---------------------------------------------------------------------------
__global__ __launch_bounds__(256) void wo_prep(const float* __restrict__ Wo)
{
    int i = (blockIdx.x * 256 + threadIdx.x) * 4;
    float4 v = *(const float4*)&Wo[i];
    *(uint2*)&g_wo16[i >> 1] = make_uint2(packh(v.x, v.y), packh(v.z, v.w));
}

// ---------------------------------------------------------------------------
// Kernel 1: per-head projections via fp16 m16n8k16 mma.
// Q gets log2e/32 folded before its bf16 rounding. Q/K out bf16x2; V fp16x2.
// grid (32, BH, 3), block 128.
// ---------------------------------------------------------------------------
__global__ __launch_bounds__(128) void proj_kernel(
    const float* __restrict__ Q, const float* __restrict__ K, const float* __restrict__ V,
    const float* __restrict__ Wq, const float* __restrict__ Wk, const float* __restrict__ Wv)
{
    __shared__ __align__(16) uint32_t Xs[64 * 36];   // fp16x2 words, stride 36
    __shared__ __align__(16) uint32_t Ws[64 * 36];

    int which = blockIdx.z;
    const float* X = (which == 0) ? Q : (which == 1) ? K : V;
    const float* W = (which == 0) ? Wq : (which == 1) ? Wk : Wv;
    int bh = blockIdx.y, b = bh >> 4, h = bh & 15;
    int n0 = blockIdx.x * 64;
    int t = threadIdx.x, w = t >> 5, lane = t & 31, g = lane >> 2, tig = lane & 3;

    const float* Xb = X + ((size_t)b * N_ + n0) * E_ + h * 64;
    for (int idx = t; idx < 1024; idx += 128) {
        int r = idx >> 4, j = idx & 15;                    // j = float4 index
        float4 x = *(const float4*)&Xb[(size_t)r * E_ + j * 4];
        *(uint2*)&Xs[r * 36 + 2 * j] = make_uint2(packh(x.x, x.y), packh(x.z, x.w));
    }
    for (int idx = t; idx < 2048; idx += 128) {
        int r = idx >> 5, wd = idx & 31;
        float2 v = *(const float2*)&W[h * 4096 + r * 64 + 2 * wd];
        Ws[r * 36 + wd] = packh(v.x, v.y);
    }
    __syncthreads();

    int r_lo = w * 16 + g, r_hi = r_lo + 8;
    float o[8][4] = {};
    #pragma unroll
    for (int kk = 0; kk < 4; kk++) {
        uint32_t a0 = Xs[r_lo * 36 + kk * 8 + tig];
        uint32_t a1 = Xs[r_hi * 36 + kk * 8 + tig];
        uint32_t a2 = Xs[r_lo * 36 + kk * 8 + tig + 4];
        uint32_t a3 = Xs[r_hi * 36 + kk * 8 + tig + 4];
        #pragma unroll
        for (int nt = 0; nt < 8; nt++) {
            uint32_t b0 = Ws[(nt * 8 + g) * 36 + kk * 8 + tig];
            uint32_t b1 = Ws[(nt * 8 + g) * 36 + kk * 8 + tig + 4];
            mma_f16(o[nt], a0, a1, a2, a3, b0, b1);
        }
    }
    size_t rb = (size_t)bh * N_ + n0;
    if (which == 2) {
        #pragma unroll
        for (int nt = 0; nt < 8; nt++) {
            g_v16[(rb + r_lo) * 32 + nt * 4 + tig] = packh(o[nt][0], o[nt][1]);
            g_v16[(rb + r_hi) * 32 + nt * 4 + tig] = packh(o[nt][2], o[nt][3]);
        }
    } else {
        uint32_t* dst = (which == 0) ? g_q16 : g_k16;
        const float C = (which == 0) ? 0.045084220027780106f : 1.0f;  // log2e/32 into Q
        #pragma unroll
        for (int nt = 0; nt < 8; nt++) {
            dst[(rb + r_lo) * 32 + nt * 4 + tig] = packbf(o[nt][0] * C, o[nt][1] * C);
            dst[(rb + r_hi) * 32 + nt * 4 + tig] = packbf(o[nt][2] * C, o[nt][3] * C);
        }
    }
}

// ---------------------------------------------------------------------------
// Kernel 2: flash attention, no-max softmax, raw MUFU.EX2.
// CTA = 256 q-rows x 64 keys; 8 warps x 32 rows.
// S: bf16 m16n8k16 (pre-scaled Q, masked rows zeroed via AND).
// PV: fp16 m16n8k16; P packed straight from registers (C-frag == A-frag).
// V: fp16 from proj; d-pairs -> key-pairs via 2 PRMT per word pair.
// grid (8, BH), block 256.
// ---------------------------------------------------------------------------
constexpr int KS_W = 64 * 36;
constexpr int VT_W = 32 * 72;

__global__ __launch_bounds__(256) void attn_kernel(const int* __restrict__ mask)
{
    __shared__ __align__(16) uint32_t Ks16[2][KS_W];
    __shared__ __align__(16) uint32_t Vt[2][VT_W];
    uint32_t kb_base = smem_u32(&Ks16[0][0]);

    int bh = blockIdx.y, b = bh >> 4, h = bh & 15;
    int q0 = blockIdx.x * 256;
    int t = threadIdx.x, wid = t >> 5, lane = t & 31, g = lane >> 2, tig = lane & 3;
    const uint32_t FULL = 0xffffffffu;

    int r0 = wid * 32 + g;
    int rows[4] = {r0, r0 + 8, r0 + 16, r0 + 24};
    uint32_t msk[4];
    #pragma unroll
    for (int i = 0; i < 4; i++)
        msk[i] = mask[b * N_ + q0 + rows[i]] ? 0xffffffffu : 0u;

    const uint32_t* Qg = g_q16 + ((size_t)bh * N_ + q0) * 32;
    uint32_t qa[2][4][4];
    #pragma unroll
    for (int m = 0; m < 2; m++)
        #pragma unroll
        for (int kk = 0; kk < 4; kk++) {
            qa[m][kk][0] = Qg[(size_t)rows[2*m]   * 32 + kk * 8 + tig]     & msk[2*m];
            qa[m][kk][1] = Qg[(size_t)rows[2*m+1] * 32 + kk * 8 + tig]     & msk[2*m+1];
            qa[m][kk][2] = Qg[(size_t)rows[2*m]   * 32 + kk * 8 + tig + 4] & msk[2*m];
            qa[m][kk][3] = Qg[(size_t)rows[2*m+1] * 32 + kk * 8 + tig + 4] & msk[2*m+1];
        }

    const uint32_t* Kg = g_k16 + (size_t)bh * N_ * 32;
    const uint32_t* Vg = g_v16 + (size_t)bh * N_ * 32;

    auto prefK = [&](int kt, int buf) {
        const uint32_t* kg = Kg + kt * 64 * 32;
        uint32_t kb = kb_base + buf * (KS_W * 4);
        #pragma unroll
        for (int i = t; i < 512; i += 256) {
            int row = i >> 3, c = (i & 7) * 4;
            cpa16(kb + (row * 36 + c) * 4, &kg[row * 32 + c]);
        }
        asm volatile("cp.async.commit_group;");
    };

    // V prefetch: lane = d-pair word (0..31), kp = wid + 8*i (key pair)
    uint32_t vA[4], vB[4];
    auto ldV = [&](int kt) {
        const uint32_t* vg = Vg + kt * 64 * 32;
        #pragma unroll
        for (int i = 0; i < 4; i++) {
            int kp = wid + 8 * i;
            vA[i] = vg[(2 * kp) * 32 + lane];        // key 2kp,   d 2lane..2lane+1
            vB[i] = vg[(2 * kp + 1) * 32 + lane];    // key 2kp+1
        }
    };
    auto stV = [&](int buf) {
        #pragma unroll
        for (int i = 0; i < 4; i++) {
            int kp = wid + 8 * i;
            uint32_t w0 = prmt(vA[i], vB[i], 0x5410);   // (v[2kp][d], v[2kp+1][d]), d=2lane
            uint32_t w1 = prmt(vA[i], vB[i], 0x7632);   // d=2lane+1
            *(uint2*)&Vt[buf][kp * 72 + 2 * lane] = make_uint2(w0, w1);
        }
    };

    float o[2][8][4] = {};
    float lr[4] = {};

    prefK(0, 0);
    ldV(0);
    for (int kt = 0; kt < 32; kt++) {
        int buf = kt & 1;
        stV(buf);
        asm volatile("cp.async.wait_group 0;");
        __syncthreads();
        if (kt + 1 < 32) { prefK(kt + 1, buf ^ 1); ldV(kt + 1); }
        const uint32_t* Kb = Ks16[buf];
        const uint32_t* Vb = Vt[buf];

        // ---- S = (Q*log2e/32) K^T (bf16 m16n8k16) ----
        float s[2][8][4] = {};
        #pragma unroll
        for (int kk = 0; kk < 4; kk++)
            #pragma unroll
            for (int nt = 0; nt < 8; nt++) {
                uint32_t b0 = Kb[(nt * 8 + g) * 36 + kk * 8 + tig];
                uint32_t b1 = Kb[(nt * 8 + g) * 36 + kk * 8 + tig + 4];
                mma_bf16(s[0][nt], qa[0][kk][0], qa[0][kk][1], qa[0][kk][2], qa[0][kk][3], b0, b1);
                mma_bf16(s[1][nt], qa[1][kk][0], qa[1][kk][1], qa[1][kk][2], qa[1][kk][3], b0, b1);
            }

        // ---- p = 2^s via raw MUFU.EX2 (no max: |s| << 1), partial l ----
        #pragma unroll
        for (int m = 0; m < 2; m++)
            #pragma unroll
            for (int nt = 0; nt < 8; nt++) {
                s[m][nt][0] = ex2(s[m][nt][0]);
                s[m][nt][1] = ex2(s[m][nt][1]);
                s[m][nt][2] = ex2(s[m][nt][2]);
                s[m][nt][3] = ex2(s[m][nt][3]);
                lr[2*m]   += s[m][nt][0] + s[m][nt][1];
                lr[2*m+1] += s[m][nt][2] + s[m][nt][3];
            }

        // ---- O += P @ V (fp16 m16n8k16, P packed straight from registers) ----
        #pragma unroll
        for (int kk = 0; kk < 4; kk++) {
            uint32_t pa[2][4];
            #pragma unroll
            for (int m = 0; m < 2; m++) {
                pa[m][0] = packh(s[m][2*kk][0],   s[m][2*kk][1]);
                pa[m][1] = packh(s[m][2*kk][2],   s[m][2*kk][3]);
                pa[m][2] = packh(s[m][2*kk+1][0], s[m][2*kk+1][1]);
                pa[m][3] = packh(s[m][2*kk+1][2], s[m][2*kk+1][3]);
            }
            #pragma unroll
            for (int nt = 0; nt < 8; nt++) {
                uint32_t b0 = Vb[(kk * 8 + tig) * 72 + nt * 8 + g];
                uint32_t b1 = Vb[(kk * 8 + tig + 4) * 72 + nt * 8 + g];
                mma_f16(o[0][nt], pa[0][0], pa[0][1], pa[0][2], pa[0][3], b0, b1);
                mma_f16(o[1][nt], pa[1][0], pa[1][1], pa[1][2], pa[1][3], b0, b1);
            }
        }
    }

    // deferred l-reduction
    float il[4];
    #pragma unroll
    for (int i = 0; i < 4; i++) {
        lr[i] += __shfl_xor_sync(FULL, lr[i], 1);
        lr[i] += __shfl_xor_sync(FULL, lr[i], 2);
        il[i] = 1.f / lr[i];
    }
    uint32_t* ob = g_at16 + ((size_t)b * N_ + q0) * 512 + h * 32;
    #pragma unroll
    for (int m = 0; m < 2; m++)
        #pragma unroll
        for (int nt = 0; nt < 8; nt++) {
            ob[(size_t)rows[2*m]   * 512 + nt * 4 + tig] =
                packh(o[m][nt][0] * il[2*m],   o[m][nt][1] * il[2*m]);
            ob[(size_t)rows[2*m+1] * 512 + nt * 4 + tig] =
                packh(o[m][nt][2] * il[2*m+1], o[m][nt][3] * il[2*m+1]);
        }
}

// ---------------------------------------------------------------------------
// Kernel 3: out = attn @ Wo^T, fp16 m16n8k16. grid (32, 8), block 256.
// ---------------------------------------------------------------------------
constexpr int OPH = 128 * 36;

__global__ __launch_bounds__(256) void oproj_kernel(float* __restrict__ out)
{
    extern __shared__ __align__(16) char smraw[];
    uint32_t* As = (uint32_t*)smraw;
    uint32_t* Ws = (uint32_t*)(smraw + 2 * OPH * 4);
    uint32_t smem_base = smem_u32(smraw);

    int rB = blockIdx.x * 128, cB = blockIdx.y * 128;
    int t = threadIdx.x, w = t >> 5, lane = t & 31, g = lane >> 2, tig = lane & 3;
    int wr = w >> 1, wc = w & 1;
    int row0 = wr * 32, col0 = wc * 64;

    auto prefetch = [&](int e0w, int buf) {
        uint32_t abase = smem_base + (buf * OPH) * 4;
        uint32_t wbase = smem_base + (2 * OPH + buf * OPH) * 4;
        #pragma unroll
        for (int i = t; i < 1024; i += 256) {
            int r = i >> 3, c = (i & 7) * 4;
            cpa16(abase + (r * 36 + c) * 4, &g_at16[(size_t)(rB + r) * 512 + e0w + c]);
        }
        #pragma unroll
        for (int i = t; i < 1024; i += 256) {
            int r = i >> 3, c = (i & 7) * 4;
            cpa16(wbase + (r * 36 + c) * 4, &g_wo16[(size_t)(cB + r) * 512 + e0w + c]);
        }
        asm volatile("cp.async.commit_group;");
    };

    float o[2][8][4] = {};
    prefetch(0, 0);
    for (int es = 0; es < 16; es++) {
        int buf = es & 1;
        if (es + 1 < 16) {
            prefetch((es + 1) * 32, buf ^ 1);
            asm volatile("cp.async.wait_group 1;");
        } else {
            asm volatile("cp.async.wait_group 0;");
        }
        __syncthreads();
        const uint32_t* Ab = As + buf * OPH;
        const uint32_t* Wb = Ws + buf * OPH;

        #pragma unroll
        for (int kk = 0; kk < 4; kk++) {
            uint32_t a[2][4];
            #pragma unroll
            for (int m = 0; m < 2; m++) {
                int ra = row0 + 16 * m + g;
                a[m][0] = Ab[ra * 36 + kk * 8 + tig];
                a[m][1] = Ab[(ra + 8) * 36 + kk * 8 + tig];
                a[m][2] = Ab[ra * 36 + kk * 8 + tig + 4];
                a[m][3] = Ab[(ra + 8) * 36 + kk * 8 + tig + 4];
            }
            #pragma unroll
            for (int nt = 0; nt < 8; nt++) {
                uint32_t b0 = Wb[(col0 + nt * 8 + g) * 36 + kk * 8 + tig];
                uint32_t b1 = Wb[(col0 + nt * 8 + g) * 36 + kk * 8 + tig + 4];
                mma_f16(o[0][nt], a[0][0], a[0][1], a[0][2], a[0][3], b0, b1);
                mma_f16(o[1][nt], a[1][0], a[1][1], a[1][2], a[1][3], b0, b1);
            }
        }
        __syncthreads();
    }

    #pragma unroll
    for (int m = 0; m < 2; m++) {
        int ra = rB + row0 + 16 * m + g;
        #pragma unroll
        for (int nt = 0; nt < 8; nt++) {
            *(float2*)&out[(size_t)ra * E_ + cB + col0 + nt * 8 + 2 * tig] =
                make_float2(o[m][nt][0], o[m][nt][1]);
            *(float2*)&out[(size_t)(ra + 8) * E_ + cB + col0 + nt * 8 + 2 * tig] =
                make_float2(o[m][nt][2], o[m][nt][3]);
        }
    }
}

// ---------------------------------------------------------------------------
extern "C" void kernel_launch(void* const* d_in, const int* in_sizes, int n_in,
                              void* d_out, int out_size)
{
    const float* q    = (const float*)d_in[0];
    const float* k    = (const float*)d_in[1];
    const float* v    = (const float*)d_in[2];
    const int*   mask = (const int*)  d_in[3];
    const float* Wq   = (const float*)d_in[4];
    const float* Wk   = (const float*)d_in[5];
    const float* Wv   = (const float*)d_in[6];
    const float* Wo   = (const float*)d_in[7];
    float* out = (float*)d_out;

    int oproj_smem = 4 * OPH * 4;                            // 73728 B
    static int attr_set = 0;
    if (!attr_set) {
        cudaFuncSetAttribute(oproj_kernel, cudaFuncAttributeMaxDynamicSharedMemorySize, oproj_smem);
        attr_set = 1;
    }

    wo_prep<<<E_ * E_ / 1024, 256>>>(Wo);
    proj_kernel<<<dim3(N_ / 64, BH, 3), 128>>>(q, k, v, Wq, Wk, Wv);
    attn_kernel<<<dim3(N_ / 256, BH), 256>>>(mask);
    oproj_kernel<<<dim3(B_ * N_ / 128, E_ / 128), 256, oproj_smem>>>(out);
}